// round 1
// baseline (speedup 1.0000x reference)
#include <cuda_runtime.h>
#include <cstdint>

// ---------------------------------------------------------------------------
// QuantLinear: out[M,T] = x[M,K] @ dequant(qweight)[K,T] + bias[T]
//   qweight: [K/8, T] int32, nibble i of row r = weight k = r*8+i  (4-bit)
//   W[k,t] = scales[k/128, t] * (q[k,t] - zeros[k/128, t])
// M=4096, K=4096, T=11008 (derived from in_sizes; all divisible by tiles)
//
// Strategy (round 0): tf32 mma.sync.m16n8k8 GEMM, fused on-the-fly dequant.
//   CTA tile 128x128x32, 8 warps (4m x 2n), warp tile 32x64.
//   A (x) tile: cp.async double-buffered SMEM, stride 36 (conflict-free frags)
//   B (W) tile: qweight int32 -> regs (LDG hidden under MMA) -> fp32 dequant
//               -> tf32 round -> SMEM stride 136 (conflict-free frags)
// ---------------------------------------------------------------------------

#define BM 128
#define BN 128
#define BK 32
#define AS_STRIDE 36    // floats per A row (32 data + 4 pad) -> bank 4g+q unique
#define BS_STRIDE 136   // floats per B row (128 data + 8 pad) -> bank 8q+g unique
#define NTHREADS 256

#define A_BUF_FLOATS (BM * AS_STRIDE)           // 4608
#define B_BUF_FLOATS (BK * BS_STRIDE)           // 4352
#define SMEM_FLOATS  (2 * A_BUF_FLOATS + 2 * B_BUF_FLOATS)
#define SMEM_BYTES   (SMEM_FLOATS * 4)          // 71680

__device__ __forceinline__ uint32_t f2tf32(float x) {
    uint32_t r;
    asm("cvt.rna.tf32.f32 %0, %1;" : "=r"(r) : "f"(x));
    return r;
}

__device__ __forceinline__ void cp_async16(uint32_t smem_addr, const void* gptr) {
    asm volatile("cp.async.cg.shared.global [%0], [%1], 16;" :: "r"(smem_addr), "l"(gptr));
}

__device__ __forceinline__ void mma_tf32(float c[4], const uint32_t a[4], const uint32_t b[2]) {
    asm volatile(
        "mma.sync.aligned.m16n8k8.row.col.f32.tf32.tf32.f32 "
        "{%0,%1,%2,%3}, {%4,%5,%6,%7}, {%8,%9}, {%0,%1,%2,%3};"
        : "+f"(c[0]), "+f"(c[1]), "+f"(c[2]), "+f"(c[3])
        : "r"(a[0]), "r"(a[1]), "r"(a[2]), "r"(a[3]), "r"(b[0]), "r"(b[1]));
}

__global__ void __launch_bounds__(NTHREADS)
qgemm_tf32_kernel(const float* __restrict__ x,
                  const int*   __restrict__ qw,
                  const float* __restrict__ scales,
                  const float* __restrict__ zeros,
                  const float* __restrict__ bias,
                  float*       __restrict__ out,
                  int M, int K, int T)
{
    extern __shared__ float smem[];
    float* As = smem;                       // [2][BM][AS_STRIDE]
    float* Bs = smem + 2 * A_BUF_FLOATS;    // [2][BK][BS_STRIDE]

    const int tid  = threadIdx.x;
    const int warp = tid >> 5;
    const int lane = tid & 31;
    const int g    = lane >> 2;     // 0..7
    const int q    = lane & 3;      // 0..3
    const int wm   = (warp & 3) * 32;   // warp m offset in CTA tile
    const int wn   = (warp >> 2) * 64;  // warp n offset in CTA tile
    const int m0   = blockIdx.y * BM;
    const int n0   = blockIdx.x * BN;

    const int NS = K / BK;          // 128 k-stages

    // dequant thread mapping: column t = tid&127 (fixed), k-rows {kr, kr+2}
    const int tcol = tid & 127;             // 0..127 within tile
    const int kr   = tid >> 7;              // 0 or 1
    const int gcol = n0 + tcol;             // global column for qw/scales/zeros

    float acc[2][8][4];
    #pragma unroll
    for (int mf = 0; mf < 2; ++mf)
        #pragma unroll
        for (int nf = 0; nf < 8; ++nf)
            #pragma unroll
            for (int i = 0; i < 4; ++i)
                acc[mf][nf][i] = 0.0f;

    // staged weight registers
    int   wreg[2];
    float screg, szreg;

    // ---- stage-load helpers (inlined manually via macros of code blocks) ----
    // load x tile (cp.async) for k-offset k0 into buffer buf
    auto load_x = [&](int buf, int k0) {
        const float* xg = x + (size_t)m0 * K + k0;
        uint32_t sbase = (uint32_t)__cvta_generic_to_shared(As + buf * A_BUF_FLOATS);
        #pragma unroll
        for (int i = 0; i < 4; ++i) {
            int c  = tid + i * NTHREADS;       // 0..1023
            int m  = c >> 3;                   // row in tile
            int kc = (c & 7) * 4;              // float offset in row
            cp_async16(sbase + (uint32_t)(m * AS_STRIDE + kc) * 4u,
                       xg + (size_t)m * K + kc);
        }
        asm volatile("cp.async.commit_group;");
    };

    // fetch packed weights + scale/zero for k-offset k0 into regs
    auto load_w = [&](int k0) {
        int rb = k0 >> 3;                      // qweight row base
        wreg[0] = __ldg(&qw[(size_t)(rb + kr) * T + gcol]);
        wreg[1] = __ldg(&qw[(size_t)(rb + kr + 2) * T + gcol]);
        int grp = k0 >> 7;                     // group = k0/128
        screg = __ldg(&scales[(size_t)grp * T + gcol]);
        float z = __ldg(&zeros[(size_t)grp * T + gcol]);
        szreg = -screg * z;
    };

    // dequant staged regs into Bs buffer buf
    auto dequant = [&](int buf) {
        float* Bp = Bs + buf * B_BUF_FLOATS + tcol;
        #pragma unroll
        for (int j = 0; j < 2; ++j) {
            int w  = wreg[j];
            int kb = (kr + 2 * j) * 8;
            #pragma unroll
            for (int i = 0; i < 8; ++i) {
                float qv = (float)((w >> (4 * i)) & 15);
                float v  = fmaf(qv, screg, szreg);
                Bp[(kb + i) * BS_STRIDE] = __uint_as_float(f2tf32(v));
            }
        }
    };

    // ---- prologue ----
    load_x(0, 0);
    load_w(0);
    asm volatile("cp.async.wait_group 0;");
    dequant(0);
    __syncthreads();

    // ---- main loop ----
    for (int s = 0; s < NS; ++s) {
        const int cb = s & 1;
        const int nb = cb ^ 1;

        if (s + 1 < NS) {
            load_x(nb, (s + 1) * BK);
            load_w((s + 1) * BK);
        }

        // compute on current buffers
        const float*    Ab = As + cb * A_BUF_FLOATS;
        const uint32_t* Bb = (const uint32_t*)(Bs + cb * B_BUF_FLOATS);
        #pragma unroll
        for (int kk = 0; kk < 4; ++kk) {
            const int kb = kk * 8;
            uint32_t bfrag[8][2];
            #pragma unroll
            for (int nf = 0; nf < 8; ++nf) {
                int n = wn + nf * 8 + g;
                bfrag[nf][0] = Bb[(kb + q) * BS_STRIDE + n];
                bfrag[nf][1] = Bb[(kb + 4 + q) * BS_STRIDE + n];
            }
            uint32_t afrag[2][4];
            #pragma unroll
            for (int mf = 0; mf < 2; ++mf) {
                int mb = wm + mf * 16 + g;
                afrag[mf][0] = f2tf32(Ab[(mb)     * AS_STRIDE + kb + q]);
                afrag[mf][1] = f2tf32(Ab[(mb + 8) * AS_STRIDE + kb + q]);
                afrag[mf][2] = f2tf32(Ab[(mb)     * AS_STRIDE + kb + q + 4]);
                afrag[mf][3] = f2tf32(Ab[(mb + 8) * AS_STRIDE + kb + q + 4]);
            }
            #pragma unroll
            for (int mf = 0; mf < 2; ++mf)
                #pragma unroll
                for (int nf = 0; nf < 8; ++nf)
                    mma_tf32(acc[mf][nf], afrag[mf], bfrag[nf]);
        }

        if (s + 1 < NS) {
            asm volatile("cp.async.wait_group 0;");
            dequant(nb);
        }
        __syncthreads();
    }

    // ---- epilogue: add bias, store fp32 ----
    #pragma unroll
    for (int mf = 0; mf < 2; ++mf) {
        #pragma unroll
        for (int nf = 0; nf < 8; ++nf) {
            int row = m0 + wm + mf * 16 + g;
            int col = n0 + wn + nf * 8 + 2 * q;
            float bx = __ldg(&bias[col]);
            float by = __ldg(&bias[col + 1]);
            float2 v0, v1;
            v0.x = acc[mf][nf][0] + bx;
            v0.y = acc[mf][nf][1] + by;
            v1.x = acc[mf][nf][2] + bx;
            v1.y = acc[mf][nf][3] + by;
            *(float2*)&out[(size_t)row * T + col]       = v0;
            *(float2*)&out[(size_t)(row + 8) * T + col] = v1;
        }
    }
}

extern "C" void kernel_launch(void* const* d_in, const int* in_sizes, int n_in,
                              void* d_out, int out_size)
{
    const float* x      = (const float*)d_in[0];
    const int*   qw     = (const int*)  d_in[1];
    const float* scales = (const float*)d_in[2];
    const float* zeros  = (const float*)d_in[3];
    const float* bias   = (const float*)d_in[4];
    float*       out    = (float*)d_out;

    const int T = in_sizes[4];                 // 11008
    const int K = (in_sizes[1] / T) * 8;       // 4096
    const int M = in_sizes[0] / K;             // 4096

    cudaFuncSetAttribute(qgemm_tf32_kernel,
                         cudaFuncAttributeMaxDynamicSharedMemorySize, SMEM_BYTES);

    dim3 grid(T / BN, M / BM);                 // 86 x 32
    qgemm_tf32_kernel<<<grid, NTHREADS, SMEM_BYTES>>>(
        x, qw, scales, zeros, bias, out, M, K, T);
}